// round 15
// baseline (speedup 1.0000x reference)
#include <cuda_runtime.h>
#include <cuda_fp16.h>
#include <math.h>
#include <stdint.h>

#define B_   8
#define N_   8192
#define C_   256
#define H_   128
#define W_   128
#define NH_  8
#define HW_  (H_ * W_)
#define M_   (B_ * N_)      // 65536
#define P96  96
#define KS   512            // wcat split store stride (hi | lo)

// ---- scratch (static device allocations; no cudaMalloc anywhere) ----
__device__ __half g_valth[(size_t)B_ * NH_ * HW_ * 32];     // (B,Hh,HW,D) fp16, 67MB
__device__ float g_params[(size_t)M_ * P96];                // [off(64) | attn(32)]
__device__ __half g_ah[(size_t)M_ * C_];                    // agg fp16 [M][256]
__device__ __half g_wc[128 * KS];                           // wcat^T splits (pad rows 96-127)
__device__ __half g_woh[C_ * C_];                           // W_out^T hi [256][256]
__device__ float g_bcat[P96];

// ============================ PTX helpers ==================================
__device__ __forceinline__ uint32_t smem_u32(const void* p) {
    uint32_t a;
    asm("{ .reg .u64 t; cvta.to.shared.u64 t, %1; cvt.u32.u64 %0, t; }"
        : "=r"(a) : "l"(p));
    return a;
}
__device__ __forceinline__ void cp16(uint32_t dst, const void* src) {
    asm volatile("cp.async.cg.shared.global [%0], [%1], 16;" :: "r"(dst), "l"(src));
}
#define CP_COMMIT() asm volatile("cp.async.commit_group;" ::: "memory")
#define CP_WAIT(n)  asm volatile("cp.async.wait_group %0;" :: "n"(n) : "memory")

__device__ __forceinline__ void ldsm4(uint32_t* r, uint32_t addr) {
    asm volatile("ldmatrix.sync.aligned.m8n8.x4.shared.b16 {%0,%1,%2,%3}, [%4];"
                 : "=r"(r[0]), "=r"(r[1]), "=r"(r[2]), "=r"(r[3]) : "r"(addr));
}
__device__ __forceinline__ void mma_f16(float* d, const uint32_t* a, const uint32_t* b) {
    asm volatile(
        "mma.sync.aligned.m16n8k16.row.col.f32.f16.f16.f32 "
        "{%0,%1,%2,%3}, {%4,%5,%6,%7}, {%8,%9}, {%0,%1,%2,%3};"
        : "+f"(d[0]), "+f"(d[1]), "+f"(d[2]), "+f"(d[3])
        : "r"(a[0]), "r"(a[1]), "r"(a[2]), "r"(a[3]), "r"(b[0]), "r"(b[1]));
}
#define STS128(addr, v) \
    asm volatile("st.shared.v4.b32 [%0], {%1,%2,%3,%4};" \
                 :: "r"(addr), "r"((v).x), "r"((v).y), "r"((v).z), "r"((v).w) : "memory")

__device__ __forceinline__ uint32_t swz(uint32_t off) { return off ^ ((off >> 3) & 0x70); }

// ============================ fp16 2-way split =============================
__device__ __forceinline__ void split2h(float v, __half& h, __half& l) {
    h = __float2half(v);
    l = __float2half(v - __half2float(h));
}

// ---------------------------------------------------------------------------
// Combined weight prep: wcat^T -> g_wc [128][512] (+bcat); W_out^T hi -> g_woh.
// ---------------------------------------------------------------------------
__global__ void prep_weights_kernel(const float* __restrict__ W_off,
                                    const float* __restrict__ b_off,
                                    const float* __restrict__ W_attn,
                                    const float* __restrict__ b_attn,
                                    const float* __restrict__ W_out) {
    int id = blockIdx.x * blockDim.x + threadIdx.x;
    if (id < 128 * 256) {
        int j = id >> 8, k = id & 255;
        float v = 0.f;
        if (j < 64)       v = W_off[k * 64 + j];
        else if (j < 96)  v = W_attn[k * 32 + (j - 64)];
        __half h, l;
        split2h(v, h, l);
        g_wc[j * KS + k] = h; g_wc[j * KS + 256 + k] = l;
        if (id < P96) g_bcat[id] = (id < 64) ? b_off[id] : b_attn[id - 64];
    } else {
        int id2 = id - 128 * 256;       // over 256*256
        int n = id2 >> 8, k = id2 & 255;
        g_woh[n * C_ + k] = __float2half(W_out[k * C_ + n]);
    }
}

// ---------------------------------------------------------------------------
// Transpose v4: (B, Hh*D, H*W) fp32 -> (B, Hh, H*W, D) fp16.
// ---------------------------------------------------------------------------
__global__ void transpose_val_kernel(const float* __restrict__ val) {
    __shared__ float4 t4[64][8];
    int bh = blockIdx.y;
    int p0 = blockIdx.x * 64;
    int tid = threadIdx.x;
    int dl = tid >> 6;         // 0..3
    int pl = tid & 63;         // 0..63
    const float* src = val + ((size_t)bh * 32) * HW_ + p0 + pl;
#pragma unroll
    for (int i = 0; i < 2; i++) {
        int dq = dl * 2 + i;   // 0..7
        float4 v;
        v.x = src[(size_t)(dq * 4 + 0) * HW_];
        v.y = src[(size_t)(dq * 4 + 1) * HW_];
        v.z = src[(size_t)(dq * 4 + 2) * HW_];
        v.w = src[(size_t)(dq * 4 + 3) * HW_];
        t4[pl][dq ^ (pl & 7)] = v;
    }
    __syncthreads();
    int c  = tid & 7;          // output d-quad
    int pw = tid >> 3;         // 0..31
    __half* dst = g_valth + (size_t)bh * HW_ * 32 + (size_t)p0 * 32;
#pragma unroll
    for (int i = 0; i < 2; i++) {
        int p = pw + i * 32;
        float4 v = t4[p][c ^ (p & 7)];
        __half2 h01 = __floats2half2_rn(v.x, v.y);
        __half2 h23 = __floats2half2_rn(v.z, v.w);
        uint2 u;
        u.x = *reinterpret_cast<uint32_t*>(&h01);
        u.y = *reinterpret_cast<uint32_t*>(&h23);
        *(uint2*)&dst[(size_t)p * 32 + c * 4] = u;
    }
}

// ===========================================================================
// GEMM-1 FUSED: params[M,96] = q_hi@w_hi + q_hi@w_lo + q_lo@w_hi + bcat.
// Reads fp32 query directly; splits in regs; 3 mma passes per 64-col chunk.
// ===========================================================================
__global__ __launch_bounds__(256)
void g1_fused_kernel(const float* __restrict__ Q,
                     const __half* __restrict__ WC,
                     const float* __restrict__ bias,
                     float* __restrict__ Cm) {
    extern __shared__ char dyn_raw[];
    const uint32_t raw = smem_u32(dyn_raw);
    const uint32_t sb  = (raw + 1023) & ~1023u;
    const uint32_t A_hi = sb;
    const uint32_t A_lo = sb + 16384;
    const uint32_t Bb   = sb + 32768;    // [st][whi|wlo] 16KB each

    const int tid  = threadIdx.x;
    const int wid  = tid >> 5;
    const int lane = tid & 31;
    const int row0 = blockIdx.y * 128;
    const int wm   = (wid >> 2) * 64;
    const int wn   = (wid & 3) * 32;

    float acc[4][4][4];
#pragma unroll
    for (int mi = 0; mi < 4; mi++)
#pragma unroll
        for (int ni = 0; ni < 4; ni++)
#pragma unroll
            for (int v = 0; v < 4; v++) acc[mi][ni][v] = 0.f;

    const int lrow = tid >> 3;          // 0..31
    const int lblk = tid & 7;           // 16B chunk

    auto loadB = [&](int c, int st) {
        uint32_t bh = Bb + st * 32768;
        uint32_t bl = bh + 16384;
        const __half* g1 = WC + (size_t)lrow * KS + c * 64 + lblk * 8;        // w_hi
        const __half* g2 = WC + (size_t)lrow * KS + 256 + c * 64 + lblk * 8;  // w_lo
#pragma unroll
        for (int i = 0; i < 4; i++) {
            int r = lrow + i * 32;
            cp16(bh + swz(r * 128 + lblk * 16), g1 + (size_t)i * 32 * KS);
            cp16(bl + swz(r * 128 + lblk * 16), g2 + (size_t)i * 32 * KS);
        }
        CP_COMMIT();
    };

    loadB(0, 0);
    loadB(1, 1);

    for (int c = 0; c < 4; c++) {
        __syncthreads();                 // previous compute done reading A tiles
#pragma unroll
        for (int v = tid; v < 1024; v += 256) {
            int r = v >> 3, blk = v & 7;
            const float* ap = Q + (size_t)(row0 + r) * 256 + c * 64 + blk * 8;
            float4 f0 = *(const float4*)(ap);
            float4 f1 = *(const float4*)(ap + 4);
            __half h[8], l[8];
            split2h(f0.x, h[0], l[0]); split2h(f0.y, h[1], l[1]);
            split2h(f0.z, h[2], l[2]); split2h(f0.w, h[3], l[3]);
            split2h(f1.x, h[4], l[4]); split2h(f1.y, h[5], l[5]);
            split2h(f1.z, h[6], l[6]); split2h(f1.w, h[7], l[7]);
            uint4 uh, ul;
            uint32_t* ph = &uh.x;
            uint32_t* pl = &ul.x;
#pragma unroll
            for (int j = 0; j < 4; j++) {
                __half2 a(h[2 * j], h[2 * j + 1]);
                __half2 b(l[2 * j], l[2 * j + 1]);
                ph[j] = *reinterpret_cast<uint32_t*>(&a);
                pl[j] = *reinterpret_cast<uint32_t*>(&b);
            }
            uint32_t so = swz(r * 128 + blk * 16);
            STS128(A_hi + so, uh);
            STS128(A_lo + so, ul);
        }
        if (c + 1 < 4) { loadB(c + 1, (c + 1) & 1); CP_WAIT(1); }
        else          { CP_WAIT(0); }
        __syncthreads();

        const uint32_t bhi = Bb + (c & 1) * 32768;
        const uint32_t blo = bhi + 16384;
        const uint32_t pa[3] = {A_hi, A_hi, A_lo};
        const uint32_t pb[3] = {bhi,  blo,  bhi};
#pragma unroll
        for (int pass = 0; pass < 3; pass++) {
            const uint32_t a_t = pa[pass];
            const uint32_t b_t = pb[pass];
#pragma unroll
            for (int ks = 0; ks < 4; ks++) {
                uint32_t af[4][4];
#pragma unroll
                for (int mi = 0; mi < 4; mi++) {
                    int r  = wm + mi * 16 + (lane & 15);
                    int kc = ks * 16 + (lane >> 4) * 8;
                    ldsm4(af[mi], a_t + swz(r * 128 + kc * 2));
                }
                uint32_t bf[4][2];
#pragma unroll
                for (int nj = 0; nj < 2; nj++) {
                    int gsel = lane >> 3;
                    int nrow = wn + (nj * 2 + (gsel >> 1)) * 8 + (lane & 7);
                    int kc   = ks * 16 + (gsel & 1) * 8;
                    uint32_t r4[4];
                    ldsm4(r4, b_t + swz(nrow * 128 + kc * 2));
                    bf[nj * 2][0]     = r4[0];
                    bf[nj * 2][1]     = r4[1];
                    bf[nj * 2 + 1][0] = r4[2];
                    bf[nj * 2 + 1][1] = r4[3];
                }
#pragma unroll
                for (int mi = 0; mi < 4; mi++)
#pragma unroll
                    for (int ni = 0; ni < 4; ni++)
                        mma_f16(acc[mi][ni], af[mi], bf[ni]);
            }
        }
    }

    const int r = lane >> 2;
    const int q = lane & 3;
#pragma unroll
    for (int mi = 0; mi < 4; mi++) {
#pragma unroll
        for (int ni = 0; ni < 4; ni++) {
            int row = row0 + wm + mi * 16 + r;
            int c   = wn + ni * 8 + 2 * q;
            if (c < P96) {
                float b0 = bias[c], b1 = bias[c + 1];
                float2 v0 = make_float2(acc[mi][ni][0] + b0, acc[mi][ni][1] + b1);
                float2 v1 = make_float2(acc[mi][ni][2] + b0, acc[mi][ni][3] + b1);
                *(float2*)&Cm[(size_t)row * P96 + c]       = v0;
                *(float2*)&Cm[(size_t)(row + 8) * P96 + c] = v1;
            }
        }
    }
}

// ===========================================================================
// GEMM-2: out[M,256] = a_h @ wo_h^T + b_out.  K=256 (4 chunks of 64),
// A = g_ah [M][256] fp16, B = g_woh [256][256]. 3-stage cp.async pipeline.
// ===========================================================================
__global__ __launch_bounds__(256, 2)
void f16_gemm2(const __half* __restrict__ A,
               const __half* __restrict__ BT,
               const float* __restrict__ bias,
               float* __restrict__ Cm) {
    extern __shared__ char dyn_raw[];
    const uint32_t raw = smem_u32(dyn_raw);
    const uint32_t sb  = (raw + 1023) & ~1023u;

    const int tid  = threadIdx.x;
    const int wid  = tid >> 5;
    const int lane = tid & 31;
    const int row0 = blockIdx.y * 128;
    const int col0 = blockIdx.x * 128;
    const int wm   = (wid >> 2) * 64;
    const int wn   = (wid & 3) * 32;

    float acc[4][4][4];
#pragma unroll
    for (int mi = 0; mi < 4; mi++)
#pragma unroll
        for (int ni = 0; ni < 4; ni++)
#pragma unroll
            for (int v = 0; v < 4; v++) acc[mi][ni][v] = 0.f;

    const int lrow = tid >> 3;
    const int lblk = tid & 7;

    auto load_stage = [&](int c, int st) {
        uint32_t a_t = sb + st * 32768;
        uint32_t b_t = a_t + 16384;
        const __half* ag = A  + (size_t)(row0 + lrow) * C_ + c * 64 + lblk * 8;
        const __half* bg = BT + (size_t)(col0 + lrow) * C_ + c * 64 + lblk * 8;
#pragma unroll
        for (int i = 0; i < 4; i++) {
            int r = lrow + i * 32;
            cp16(a_t + swz(r * 128 + lblk * 16), ag + (size_t)i * 32 * C_);
            cp16(b_t + swz(r * 128 + lblk * 16), bg + (size_t)i * 32 * C_);
        }
        CP_COMMIT();
    };

    load_stage(0, 0);
    load_stage(1, 1);

    for (int c = 0; c < 4; c++) {
        if (c + 1 < 4) { CP_WAIT(1); } else { CP_WAIT(0); }
        __syncthreads();
        if (c + 2 < 4) load_stage(c + 2, (c + 2) % 3);

        const uint32_t a_t = sb + (c % 3) * 32768;
        const uint32_t b_t = a_t + 16384;
#pragma unroll
        for (int ks = 0; ks < 4; ks++) {
            uint32_t af[4][4];
#pragma unroll
            for (int mi = 0; mi < 4; mi++) {
                int r  = wm + mi * 16 + (lane & 15);
                int kc = ks * 16 + (lane >> 4) * 8;
                ldsm4(af[mi], a_t + swz(r * 128 + kc * 2));
            }
            uint32_t bf[4][2];
#pragma unroll
            for (int nj = 0; nj < 2; nj++) {
                int gsel = lane >> 3;
                int nrow = wn + (nj * 2 + (gsel >> 1)) * 8 + (lane & 7);
                int kc   = ks * 16 + (gsel & 1) * 8;
                uint32_t r4[4];
                ldsm4(r4, b_t + swz(nrow * 128 + kc * 2));
                bf[nj * 2][0]     = r4[0];
                bf[nj * 2][1]     = r4[1];
                bf[nj * 2 + 1][0] = r4[2];
                bf[nj * 2 + 1][1] = r4[3];
            }
#pragma unroll
            for (int mi = 0; mi < 4; mi++)
#pragma unroll
                for (int ni = 0; ni < 4; ni++)
                    mma_f16(acc[mi][ni], af[mi], bf[ni]);
        }
    }

    const int r = lane >> 2;
    const int q = lane & 3;
#pragma unroll
    for (int mi = 0; mi < 4; mi++) {
#pragma unroll
        for (int ni = 0; ni < 4; ni++) {
            int row = row0 + wm + mi * 16 + r;
            int c   = col0 + wn + ni * 8 + 2 * q;
            float b0 = bias[c], b1 = bias[c + 1];
            float2 v0 = make_float2(acc[mi][ni][0] + b0, acc[mi][ni][1] + b1);
            float2 v1 = make_float2(acc[mi][ni][2] + b0, acc[mi][ni][3] + b1);
            *(float2*)&Cm[(size_t)row * C_ + c]       = v0;
            *(float2*)&Cm[(size_t)(row + 8) * C_ + c] = v1;
        }
    }
}

// ---------------------------------------------------------------------------
// Sampling v5: HALF-WARP item, lane-specialized point math.
// Lane = (corner g = (lane>>2)&3, quad q = lane&3). Lane computes softmax
// weight and bilinear coords ONLY for point p=q at corner g (one exp, one
// coord chain), then 8 shuffles distribute all 4 points' (wc, idx) across
// the q-cluster. Gathers: lane loads uint4 (8 halves at d8=q*8) per point.
// Reduce xor 4,8 across corners; g==0 lanes store plain fp16 agg [M][256].
// ---------------------------------------------------------------------------
__global__ void sample_kernel(const float* __restrict__ refp) {
    int gw   = (blockIdx.x * blockDim.x + threadIdx.x) >> 5;
    int lane = threadIdx.x & 31;
    int sub  = lane >> 4;
    int it   = gw * 2 + sub;
    int h    = it & 7;
    int bn   = it >> 3;
    int b    = bn >> 13;

    int g  = (lane >> 2) & 3;
    int gx = g & 1, gy = g >> 1;
    int q  = lane & 3;
    int d8 = q * 8;

    const float* pr = g_params + (size_t)bn * P96;

    float2 rp = *(const float2*)&refp[2 * bn];
    float bx = 2.f * rp.x;
    float by = 2.f * rp.y;

    // softmax over points, distributed: lane owns logit of point q
    float lq = pr[64 + h * 4 + q];
    float mx = lq;
    mx = fmaxf(mx, __shfl_xor_sync(0xffffffffu, mx, 1));
    mx = fmaxf(mx, __shfl_xor_sync(0xffffffffu, mx, 2));
    float e = __expf(lq - mx);
    float s = e;
    s += __shfl_xor_sync(0xffffffffu, s, 1);
    s += __shfl_xor_sync(0xffffffffu, s, 2);
    float aw = e * (1.f / s);

    // coords for point q at corner g
    float2 off = *(const float2*)&pr[(h * 4 + q) * 2];
    float x = fmaf(bx + off.x, (float)W_ * 0.5f, -0.5f);
    float y = fmaf(by + off.y, (float)H_ * 0.5f, -0.5f);
    float x0f = floorf(x), y0f = floorf(y);
    float wx = x - x0f, wy = y - y0f;
    int xc = (int)x0f + gx;
    int yc = (int)y0f + gy;
    float wcx = gx ? wx : 1.f - wx;
    float wcy = gy ? wy : 1.f - wy;
    bool valid = (xc >= 0) & (xc < W_) & (yc >= 0) & (yc < H_);
    float wc_own  = valid ? (wcx * wcy * aw) : 0.f;
    int   idx_own = valid ? (yc * W_ + xc) : 0;

    // distribute (wc, idx) of all 4 points within the q-cluster (same g)
    float wcv[4];
    int   idxv[4];
#pragma unroll
    for (int p = 0; p < 4; p++) {
        int srcl = (lane & ~3) | p;
        wcv[p]  = __shfl_sync(0xffffffffu, wc_own, srcl);
        idxv[p] = __shfl_sync(0xffffffffu, idx_own, srcl);
    }

    const __half* vb = g_valth + (size_t)(b * NH_ + h) * HW_ * 32;

    uint4 vv[4];
#pragma unroll
    for (int p = 0; p < 4; p++)
        vv[p] = *(const uint4*)&vb[(size_t)idxv[p] * 32 + d8];

    float acc[8];
#pragma unroll
    for (int j = 0; j < 8; j++) acc[j] = 0.f;
#pragma unroll
    for (int p = 0; p < 4; p++) {
        float wc = wcv[p];
        const uint32_t* u = &vv[p].x;
#pragma unroll
        for (int j = 0; j < 4; j++) {
            float2 f = __half22float2(*reinterpret_cast<const __half2*>(&u[j]));
            acc[2 * j]     = fmaf(wc, f.x, acc[2 * j]);
            acc[2 * j + 1] = fmaf(wc, f.y, acc[2 * j + 1]);
        }
    }

    // reduce across corner groups (xor 4, 8 within the 16-lane item)
#pragma unroll
    for (int off2 = 4; off2 <= 8; off2 <<= 1)
#pragma unroll
        for (int j = 0; j < 8; j++)
            acc[j] += __shfl_xor_sync(0xffffffffu, acc[j], off2);

    if (g == 0) {
        uint4 uh;
        uint32_t* ph = &uh.x;
#pragma unroll
        for (int j = 0; j < 4; j++) {
            __half2 a = __floats2half2_rn(acc[2 * j], acc[2 * j + 1]);
            ph[j] = *reinterpret_cast<uint32_t*>(&a);
        }
        *(uint4*)&g_ah[(size_t)bn * C_ + h * 32 + d8] = uh;
    }
}

// ---------------------------------------------------------------------------
extern "C" void kernel_launch(void* const* d_in, const int* in_sizes, int n_in,
                              void* d_out, int out_size) {
    const float* query  = (const float*)d_in[0];
    const float* refp   = (const float*)d_in[1];
    const float* value  = (const float*)d_in[2];
    const float* W_off  = (const float*)d_in[3];
    const float* b_off  = (const float*)d_in[4];
    const float* W_attn = (const float*)d_in[5];
    const float* b_attn = (const float*)d_in[6];
    const float* W_out  = (const float*)d_in[7];
    const float* b_out  = (const float*)d_in[8];
    float* out = (float*)d_out;

    __half *wc, *woh, *ah;
    float *params, *bcat;
    cudaGetSymbolAddress((void**)&wc, g_wc);
    cudaGetSymbolAddress((void**)&woh, g_woh);
    cudaGetSymbolAddress((void**)&ah, g_ah);
    cudaGetSymbolAddress((void**)&params, g_params);
    cudaGetSymbolAddress((void**)&bcat, g_bcat);

    const int SMEM_G1 = 32768 + 65536 + 1024;   // A hi/lo + B 2-stage + pad
    const int SMEM_G2 = 3 * 32768 + 1024;       // 3-stage pipeline + pad
    cudaFuncSetAttribute(g1_fused_kernel,
                         cudaFuncAttributeMaxDynamicSharedMemorySize, SMEM_G1);
    cudaFuncSetAttribute(f16_gemm2,
                         cudaFuncAttributeMaxDynamicSharedMemorySize, SMEM_G2);

    prep_weights_kernel<<<(128 * 256 + 256 * 256) / 256, 256>>>(
        W_off, b_off, W_attn, b_attn, W_out);
    transpose_val_kernel<<<dim3(HW_ / 64, B_ * NH_), 256>>>(value);

    // GEMM-1 (fused split): params[M,96]
    g1_fused_kernel<<<dim3(1, M_ / 128), 256, SMEM_G1>>>(query, wc, bcat, params);

    // 2 items per warp -> 16 items per 256-thread block
    sample_kernel<<<(B_ * NH_ * N_) / 16, 256>>>(refp);

    // GEMM-2: out[M,256] = a_h @ wo_h + b_out  (K=256)
    f16_gemm2<<<dim3(2, M_ / 128), 256, SMEM_G2>>>(ah, woh, b_out, out);
}

// round 16
// speedup vs baseline: 1.4883x; 1.4883x over previous
#include <cuda_runtime.h>
#include <cuda_fp16.h>
#include <math.h>
#include <stdint.h>

#define B_   8
#define N_   8192
#define C_   256
#define H_   128
#define W_   128
#define NH_  8
#define HW_  (H_ * W_)
#define M_   (B_ * N_)      // 65536
#define P96  96
#define KS   512            // wcat split store stride (hi | lo)

// ---- scratch (static device allocations; no cudaMalloc anywhere) ----
__device__ __half g_valth[(size_t)B_ * NH_ * HW_ * 32];     // (B,Hh,HW,D) fp16, 67MB
__device__ float g_params[(size_t)M_ * P96];                // [off(64) | attn(32)]
__device__ __half g_ah[(size_t)M_ * C_];                    // agg fp16 [M][256]
__device__ __half g_wc[128 * KS];                           // wcat^T splits (pad rows 96-127)
__device__ __half g_woh[C_ * C_];                           // W_out^T hi [256][256]
__device__ float g_bcat[P96];

// ============================ PTX helpers ==================================
__device__ __forceinline__ uint32_t smem_u32(const void* p) {
    uint32_t a;
    asm("{ .reg .u64 t; cvta.to.shared.u64 t, %1; cvt.u32.u64 %0, t; }"
        : "=r"(a) : "l"(p));
    return a;
}
__device__ __forceinline__ void cp16(uint32_t dst, const void* src) {
    asm volatile("cp.async.cg.shared.global [%0], [%1], 16;" :: "r"(dst), "l"(src));
}
#define CP_COMMIT() asm volatile("cp.async.commit_group;" ::: "memory")
#define CP_WAIT(n)  asm volatile("cp.async.wait_group %0;" :: "n"(n) : "memory")

__device__ __forceinline__ void ldsm4(uint32_t* r, uint32_t addr) {
    asm volatile("ldmatrix.sync.aligned.m8n8.x4.shared.b16 {%0,%1,%2,%3}, [%4];"
                 : "=r"(r[0]), "=r"(r[1]), "=r"(r[2]), "=r"(r[3]) : "r"(addr));
}
__device__ __forceinline__ void mma_f16(float* d, const uint32_t* a, const uint32_t* b) {
    asm volatile(
        "mma.sync.aligned.m16n8k16.row.col.f32.f16.f16.f32 "
        "{%0,%1,%2,%3}, {%4,%5,%6,%7}, {%8,%9}, {%0,%1,%2,%3};"
        : "+f"(d[0]), "+f"(d[1]), "+f"(d[2]), "+f"(d[3])
        : "r"(a[0]), "r"(a[1]), "r"(a[2]), "r"(a[3]), "r"(b[0]), "r"(b[1]));
}
#define STS128(addr, v) \
    asm volatile("st.shared.v4.b32 [%0], {%1,%2,%3,%4};" \
                 :: "r"(addr), "r"((v).x), "r"((v).y), "r"((v).z), "r"((v).w) : "memory")

__device__ __forceinline__ uint32_t swz(uint32_t off) { return off ^ ((off >> 3) & 0x70); }

// ============================ fp16 2-way split =============================
__device__ __forceinline__ void split2h(float v, __half& h, __half& l) {
    h = __float2half(v);
    l = __float2half(v - __half2float(h));
}

// ---------------------------------------------------------------------------
// Combined weight prep: wcat^T -> g_wc [128][512] (+bcat); W_out^T hi -> g_woh.
// ---------------------------------------------------------------------------
__global__ void prep_weights_kernel(const float* __restrict__ W_off,
                                    const float* __restrict__ b_off,
                                    const float* __restrict__ W_attn,
                                    const float* __restrict__ b_attn,
                                    const float* __restrict__ W_out) {
    int id = blockIdx.x * blockDim.x + threadIdx.x;
    if (id < 128 * 256) {
        int j = id >> 8, k = id & 255;
        float v = 0.f;
        if (j < 64)       v = W_off[k * 64 + j];
        else if (j < 96)  v = W_attn[k * 32 + (j - 64)];
        __half h, l;
        split2h(v, h, l);
        g_wc[j * KS + k] = h; g_wc[j * KS + 256 + k] = l;
        if (id < P96) g_bcat[id] = (id < 64) ? b_off[id] : b_attn[id - 64];
    } else {
        int id2 = id - 128 * 256;       // over 256*256
        int n = id2 >> 8, k = id2 & 255;
        g_woh[n * C_ + k] = __float2half(W_out[k * C_ + n]);
    }
}

// ---------------------------------------------------------------------------
// Transpose v4: (B, Hh*D, H*W) fp32 -> (B, Hh, H*W, D) fp16.
// ---------------------------------------------------------------------------
__global__ void transpose_val_kernel(const float* __restrict__ val) {
    __shared__ float4 t4[64][8];
    int bh = blockIdx.y;
    int p0 = blockIdx.x * 64;
    int tid = threadIdx.x;
    int dl = tid >> 6;         // 0..3
    int pl = tid & 63;         // 0..63
    const float* src = val + ((size_t)bh * 32) * HW_ + p0 + pl;
#pragma unroll
    for (int i = 0; i < 2; i++) {
        int dq = dl * 2 + i;   // 0..7
        float4 v;
        v.x = src[(size_t)(dq * 4 + 0) * HW_];
        v.y = src[(size_t)(dq * 4 + 1) * HW_];
        v.z = src[(size_t)(dq * 4 + 2) * HW_];
        v.w = src[(size_t)(dq * 4 + 3) * HW_];
        t4[pl][dq ^ (pl & 7)] = v;
    }
    __syncthreads();
    int c  = tid & 7;          // output d-quad
    int pw = tid >> 3;         // 0..31
    __half* dst = g_valth + (size_t)bh * HW_ * 32 + (size_t)p0 * 32;
#pragma unroll
    for (int i = 0; i < 2; i++) {
        int p = pw + i * 32;
        float4 v = t4[p][c ^ (p & 7)];
        __half2 h01 = __floats2half2_rn(v.x, v.y);
        __half2 h23 = __floats2half2_rn(v.z, v.w);
        uint2 u;
        u.x = *reinterpret_cast<uint32_t*>(&h01);
        u.y = *reinterpret_cast<uint32_t*>(&h23);
        *(uint2*)&dst[(size_t)p * 32 + c * 4] = u;
    }
}

// ===========================================================================
// GEMM-1 FUSED: params[M,96] = q_hi@w_hi + q_hi@w_lo + q_lo@w_hi + bcat.
// Reads fp32 query directly; splits in regs; 3 mma passes per 64-col chunk.
// ===========================================================================
__global__ __launch_bounds__(256)
void g1_fused_kernel(const float* __restrict__ Q,
                     const __half* __restrict__ WC,
                     const float* __restrict__ bias,
                     float* __restrict__ Cm) {
    extern __shared__ char dyn_raw[];
    const uint32_t raw = smem_u32(dyn_raw);
    const uint32_t sb  = (raw + 1023) & ~1023u;
    const uint32_t A_hi = sb;
    const uint32_t A_lo = sb + 16384;
    const uint32_t Bb   = sb + 32768;    // [st][whi|wlo] 16KB each

    const int tid  = threadIdx.x;
    const int wid  = tid >> 5;
    const int lane = tid & 31;
    const int row0 = blockIdx.y * 128;
    const int wm   = (wid >> 2) * 64;
    const int wn   = (wid & 3) * 32;

    float acc[4][4][4];
#pragma unroll
    for (int mi = 0; mi < 4; mi++)
#pragma unroll
        for (int ni = 0; ni < 4; ni++)
#pragma unroll
            for (int v = 0; v < 4; v++) acc[mi][ni][v] = 0.f;

    const int lrow = tid >> 3;          // 0..31
    const int lblk = tid & 7;           // 16B chunk

    auto loadB = [&](int c, int st) {
        uint32_t bh = Bb + st * 32768;
        uint32_t bl = bh + 16384;
        const __half* g1 = WC + (size_t)lrow * KS + c * 64 + lblk * 8;        // w_hi
        const __half* g2 = WC + (size_t)lrow * KS + 256 + c * 64 + lblk * 8;  // w_lo
#pragma unroll
        for (int i = 0; i < 4; i++) {
            int r = lrow + i * 32;
            cp16(bh + swz(r * 128 + lblk * 16), g1 + (size_t)i * 32 * KS);
            cp16(bl + swz(r * 128 + lblk * 16), g2 + (size_t)i * 32 * KS);
        }
        CP_COMMIT();
    };

    loadB(0, 0);
    loadB(1, 1);

    for (int c = 0; c < 4; c++) {
        __syncthreads();                 // previous compute done reading A tiles
#pragma unroll
        for (int v = tid; v < 1024; v += 256) {
            int r = v >> 3, blk = v & 7;
            const float* ap = Q + (size_t)(row0 + r) * 256 + c * 64 + blk * 8;
            float4 f0 = *(const float4*)(ap);
            float4 f1 = *(const float4*)(ap + 4);
            __half h[8], l[8];
            split2h(f0.x, h[0], l[0]); split2h(f0.y, h[1], l[1]);
            split2h(f0.z, h[2], l[2]); split2h(f0.w, h[3], l[3]);
            split2h(f1.x, h[4], l[4]); split2h(f1.y, h[5], l[5]);
            split2h(f1.z, h[6], l[6]); split2h(f1.w, h[7], l[7]);
            uint4 uh, ul;
            uint32_t* ph = &uh.x;
            uint32_t* pl = &ul.x;
#pragma unroll
            for (int j = 0; j < 4; j++) {
                __half2 a(h[2 * j], h[2 * j + 1]);
                __half2 b(l[2 * j], l[2 * j + 1]);
                ph[j] = *reinterpret_cast<uint32_t*>(&a);
                pl[j] = *reinterpret_cast<uint32_t*>(&b);
            }
            uint32_t so = swz(r * 128 + blk * 16);
            STS128(A_hi + so, uh);
            STS128(A_lo + so, ul);
        }
        if (c + 1 < 4) { loadB(c + 1, (c + 1) & 1); CP_WAIT(1); }
        else          { CP_WAIT(0); }
        __syncthreads();

        const uint32_t bhi = Bb + (c & 1) * 32768;
        const uint32_t blo = bhi + 16384;
        const uint32_t pa[3] = {A_hi, A_hi, A_lo};
        const uint32_t pb[3] = {bhi,  blo,  bhi};
#pragma unroll
        for (int pass = 0; pass < 3; pass++) {
            const uint32_t a_t = pa[pass];
            const uint32_t b_t = pb[pass];
#pragma unroll
            for (int ks = 0; ks < 4; ks++) {
                uint32_t af[4][4];
#pragma unroll
                for (int mi = 0; mi < 4; mi++) {
                    int r  = wm + mi * 16 + (lane & 15);
                    int kc = ks * 16 + (lane >> 4) * 8;
                    ldsm4(af[mi], a_t + swz(r * 128 + kc * 2));
                }
                uint32_t bf[4][2];
#pragma unroll
                for (int nj = 0; nj < 2; nj++) {
                    int gsel = lane >> 3;
                    int nrow = wn + (nj * 2 + (gsel >> 1)) * 8 + (lane & 7);
                    int kc   = ks * 16 + (gsel & 1) * 8;
                    uint32_t r4[4];
                    ldsm4(r4, b_t + swz(nrow * 128 + kc * 2));
                    bf[nj * 2][0]     = r4[0];
                    bf[nj * 2][1]     = r4[1];
                    bf[nj * 2 + 1][0] = r4[2];
                    bf[nj * 2 + 1][1] = r4[3];
                }
#pragma unroll
                for (int mi = 0; mi < 4; mi++)
#pragma unroll
                    for (int ni = 0; ni < 4; ni++)
                        mma_f16(acc[mi][ni], af[mi], bf[ni]);
            }
        }
    }

    const int r = lane >> 2;
    const int q = lane & 3;
#pragma unroll
    for (int mi = 0; mi < 4; mi++) {
#pragma unroll
        for (int ni = 0; ni < 4; ni++) {
            int row = row0 + wm + mi * 16 + r;
            int c   = wn + ni * 8 + 2 * q;
            if (c < P96) {
                float b0 = bias[c], b1 = bias[c + 1];
                float2 v0 = make_float2(acc[mi][ni][0] + b0, acc[mi][ni][1] + b1);
                float2 v1 = make_float2(acc[mi][ni][2] + b0, acc[mi][ni][3] + b1);
                *(float2*)&Cm[(size_t)row * P96 + c]       = v0;
                *(float2*)&Cm[(size_t)(row + 8) * P96 + c] = v1;
            }
        }
    }
}

// ===========================================================================
// GEMM-2: out[M,256] = a_h @ wo_h^T + b_out.  K=256 (4 chunks of 64),
// A = g_ah [M][256] fp16, B = g_woh [256][256]. 3-stage cp.async pipeline.
// ===========================================================================
__global__ __launch_bounds__(256, 2)
void f16_gemm2(const __half* __restrict__ A,
               const __half* __restrict__ BT,
               const float* __restrict__ bias,
               float* __restrict__ Cm) {
    extern __shared__ char dyn_raw[];
    const uint32_t raw = smem_u32(dyn_raw);
    const uint32_t sb  = (raw + 1023) & ~1023u;

    const int tid  = threadIdx.x;
    const int wid  = tid >> 5;
    const int lane = tid & 31;
    const int row0 = blockIdx.y * 128;
    const int col0 = blockIdx.x * 128;
    const int wm   = (wid >> 2) * 64;
    const int wn   = (wid & 3) * 32;

    float acc[4][4][4];
#pragma unroll
    for (int mi = 0; mi < 4; mi++)
#pragma unroll
        for (int ni = 0; ni < 4; ni++)
#pragma unroll
            for (int v = 0; v < 4; v++) acc[mi][ni][v] = 0.f;

    const int lrow = tid >> 3;
    const int lblk = tid & 7;

    auto load_stage = [&](int c, int st) {
        uint32_t a_t = sb + st * 32768;
        uint32_t b_t = a_t + 16384;
        const __half* ag = A  + (size_t)(row0 + lrow) * C_ + c * 64 + lblk * 8;
        const __half* bg = BT + (size_t)(col0 + lrow) * C_ + c * 64 + lblk * 8;
#pragma unroll
        for (int i = 0; i < 4; i++) {
            int r = lrow + i * 32;
            cp16(a_t + swz(r * 128 + lblk * 16), ag + (size_t)i * 32 * C_);
            cp16(b_t + swz(r * 128 + lblk * 16), bg + (size_t)i * 32 * C_);
        }
        CP_COMMIT();
    };

    load_stage(0, 0);
    load_stage(1, 1);

    for (int c = 0; c < 4; c++) {
        if (c + 1 < 4) { CP_WAIT(1); } else { CP_WAIT(0); }
        __syncthreads();
        if (c + 2 < 4) load_stage(c + 2, (c + 2) % 3);

        const uint32_t a_t = sb + (c % 3) * 32768;
        const uint32_t b_t = a_t + 16384;
#pragma unroll
        for (int ks = 0; ks < 4; ks++) {
            uint32_t af[4][4];
#pragma unroll
            for (int mi = 0; mi < 4; mi++) {
                int r  = wm + mi * 16 + (lane & 15);
                int kc = ks * 16 + (lane >> 4) * 8;
                ldsm4(af[mi], a_t + swz(r * 128 + kc * 2));
            }
            uint32_t bf[4][2];
#pragma unroll
            for (int nj = 0; nj < 2; nj++) {
                int gsel = lane >> 3;
                int nrow = wn + (nj * 2 + (gsel >> 1)) * 8 + (lane & 7);
                int kc   = ks * 16 + (gsel & 1) * 8;
                uint32_t r4[4];
                ldsm4(r4, b_t + swz(nrow * 128 + kc * 2));
                bf[nj * 2][0]     = r4[0];
                bf[nj * 2][1]     = r4[1];
                bf[nj * 2 + 1][0] = r4[2];
                bf[nj * 2 + 1][1] = r4[3];
            }
#pragma unroll
            for (int mi = 0; mi < 4; mi++)
#pragma unroll
                for (int ni = 0; ni < 4; ni++)
                    mma_f16(acc[mi][ni], af[mi], bf[ni]);
        }
    }

    const int r = lane >> 2;
    const int q = lane & 3;
#pragma unroll
    for (int mi = 0; mi < 4; mi++) {
#pragma unroll
        for (int ni = 0; ni < 4; ni++) {
            int row = row0 + wm + mi * 16 + r;
            int c   = col0 + wn + ni * 8 + 2 * q;
            float b0 = bias[c], b1 = bias[c + 1];
            float2 v0 = make_float2(acc[mi][ni][0] + b0, acc[mi][ni][1] + b1);
            float2 v1 = make_float2(acc[mi][ni][2] + b0, acc[mi][ni][3] + b1);
            *(float2*)&Cm[(size_t)row * C_ + c]       = v0;
            *(float2*)&Cm[(size_t)(row + 8) * C_ + c] = v1;
        }
    }
}

// ---------------------------------------------------------------------------
// Sampling v3-final (proven dataflow): HALF-WARP <-> (b, n, head).
// Per-lane full softmax + coord chains (NO distribution shuffles — R15
// showed SHFL/MIO is the scarce resource), corner g=(lane>>2)&3, lane loads
// uint4 (8 halves at d8). Only the 2-round corner reduction uses shuffles.
// Epilogue: plain fp16 agg store (single uint4).
// ---------------------------------------------------------------------------
__global__ void sample_kernel(const float* __restrict__ refp) {
    int gw   = (blockIdx.x * blockDim.x + threadIdx.x) >> 5;
    int lane = threadIdx.x & 31;
    int sub  = lane >> 4;
    int it   = gw * 2 + sub;
    int h    = it & 7;
    int bn   = it >> 3;
    int b    = bn >> 13;

    int g  = (lane >> 2) & 3;
    int gx = g & 1, gy = g >> 1;
    int d8 = (lane & 3) * 8;

    const float* pr = g_params + (size_t)bn * P96;

    float2 rp = *(const float2*)&refp[2 * bn];
    float bx = 2.f * rp.x;
    float by = 2.f * rp.y;

    const float* al = pr + 64 + h * 4;
    float l0 = al[0], l1 = al[1], l2 = al[2], l3 = al[3];
    float mx = fmaxf(fmaxf(l0, l1), fmaxf(l2, l3));
    float e0 = __expf(l0 - mx), e1 = __expf(l1 - mx);
    float e2 = __expf(l2 - mx), e3 = __expf(l3 - mx);
    float inv = 1.f / (e0 + e1 + e2 + e3);
    float aw[4] = {e0 * inv, e1 * inv, e2 * inv, e3 * inv};

    const __half* vb = g_valth + (size_t)(b * NH_ + h) * HW_ * 32;

    float wcv[4];
    int   idxv[4];
#pragma unroll
    for (int p = 0; p < 4; p++) {
        float ox = pr[(h * 4 + p) * 2];
        float oy = pr[(h * 4 + p) * 2 + 1];
        float x = fmaf(bx + ox, (float)W_ * 0.5f, -0.5f);
        float y = fmaf(by + oy, (float)H_ * 0.5f, -0.5f);
        float x0f = floorf(x), y0f = floorf(y);
        float wx = x - x0f, wy = y - y0f;
        int xc = (int)x0f + gx;
        int yc = (int)y0f + gy;
        float wcx = gx ? wx : 1.f - wx;
        float wcy = gy ? wy : 1.f - wy;
        bool valid = (xc >= 0) & (xc < W_) & (yc >= 0) & (yc < H_);
        wcv[p]  = valid ? (wcx * wcy * aw[p]) : 0.f;
        idxv[p] = valid ? (yc * W_ + xc) : 0;
    }
    uint4 vv[4];
#pragma unroll
    for (int p = 0; p < 4; p++)
        vv[p] = *(const uint4*)&vb[(size_t)idxv[p] * 32 + d8];
    float acc[8];
#pragma unroll
    for (int j = 0; j < 8; j++) acc[j] = 0.f;
#pragma unroll
    for (int p = 0; p < 4; p++) {
        float wc = wcv[p];
        const uint32_t* u = &vv[p].x;
#pragma unroll
        for (int j = 0; j < 4; j++) {
            float2 f = __half22float2(*reinterpret_cast<const __half2*>(&u[j]));
            acc[2 * j]     = fmaf(wc, f.x, acc[2 * j]);
            acc[2 * j + 1] = fmaf(wc, f.y, acc[2 * j + 1]);
        }
    }

#pragma unroll
    for (int off = 4; off <= 8; off <<= 1)
#pragma unroll
        for (int j = 0; j < 8; j++)
            acc[j] += __shfl_xor_sync(0xffffffffu, acc[j], off);

    if (g == 0) {
        uint4 uh;
        uint32_t* ph = &uh.x;
#pragma unroll
        for (int j = 0; j < 4; j++) {
            __half2 a = __floats2half2_rn(acc[2 * j], acc[2 * j + 1]);
            ph[j] = *reinterpret_cast<uint32_t*>(&a);
        }
        *(uint4*)&g_ah[(size_t)bn * C_ + h * 32 + d8] = uh;
    }
}

// ---------------------------------------------------------------------------
extern "C" void kernel_launch(void* const* d_in, const int* in_sizes, int n_in,
                              void* d_out, int out_size) {
    const float* query  = (const float*)d_in[0];
    const float* refp   = (const float*)d_in[1];
    const float* value  = (const float*)d_in[2];
    const float* W_off  = (const float*)d_in[3];
    const float* b_off  = (const float*)d_in[4];
    const float* W_attn = (const float*)d_in[5];
    const float* b_attn = (const float*)d_in[6];
    const float* W_out  = (const float*)d_in[7];
    const float* b_out  = (const float*)d_in[8];
    float* out = (float*)d_out;

    __half *wc, *woh, *ah;
    float *params, *bcat;
    cudaGetSymbolAddress((void**)&wc, g_wc);
    cudaGetSymbolAddress((void**)&woh, g_woh);
    cudaGetSymbolAddress((void**)&ah, g_ah);
    cudaGetSymbolAddress((void**)&params, g_params);
    cudaGetSymbolAddress((void**)&bcat, g_bcat);

    const int SMEM_G1 = 32768 + 65536 + 1024;   // A hi/lo + B 2-stage + pad
    const int SMEM_G2 = 3 * 32768 + 1024;       // 3-stage pipeline + pad
    cudaFuncSetAttribute(g1_fused_kernel,
                         cudaFuncAttributeMaxDynamicSharedMemorySize, SMEM_G1);
    cudaFuncSetAttribute(f16_gemm2,
                         cudaFuncAttributeMaxDynamicSharedMemorySize, SMEM_G2);

    prep_weights_kernel<<<(128 * 256 + 256 * 256) / 256, 256>>>(
        W_off, b_off, W_attn, b_attn, W_out);
    transpose_val_kernel<<<dim3(HW_ / 64, B_ * NH_), 256>>>(value);

    // GEMM-1 (fused split): params[M,96]
    g1_fused_kernel<<<dim3(1, M_ / 128), 256, SMEM_G1>>>(query, wc, bcat, params);

    // 2 items per warp -> 16 items per 256-thread block
    sample_kernel<<<(B_ * NH_ * N_) / 16, 256>>>(refp);

    // GEMM-2: out[M,256] = a_h @ wo_h + b_out  (K=256)
    f16_gemm2<<<dim3(2, M_ / 128), 256, SMEM_G2>>>(ah, woh, b_out, out);
}

// round 17
// speedup vs baseline: 1.5833x; 1.0638x over previous
#include <cuda_runtime.h>
#include <cuda_fp16.h>
#include <math.h>
#include <stdint.h>

#define B_   8
#define N_   8192
#define C_   256
#define H_   128
#define W_   128
#define NH_  8
#define HW_  (H_ * W_)
#define M_   (B_ * N_)      // 65536
#define P96  96
#define KS   512            // wcat split store stride (hi | lo)

// ---- scratch (static device allocations; no cudaMalloc anywhere) ----
__device__ __half g_valth[(size_t)B_ * NH_ * HW_ * 32];     // (B,Hh,HW,D) fp16, 67MB
__device__ float g_params[(size_t)M_ * P96];                // [off(64) | attn(32)]
__device__ __half g_ah[(size_t)M_ * C_];                    // agg fp16 [M][256]
__device__ __half g_wc[128 * KS];                           // wcat^T splits (pad rows 96-127)
__device__ __half g_woh[C_ * C_];                           // W_out^T hi [256][256]
__device__ float g_bcat[P96];

// ============================ PTX helpers ==================================
__device__ __forceinline__ uint32_t smem_u32(const void* p) {
    uint32_t a;
    asm("{ .reg .u64 t; cvta.to.shared.u64 t, %1; cvt.u32.u64 %0, t; }"
        : "=r"(a) : "l"(p));
    return a;
}
__device__ __forceinline__ void cp16(uint32_t dst, const void* src) {
    asm volatile("cp.async.cg.shared.global [%0], [%1], 16;" :: "r"(dst), "l"(src));
}
#define CP_COMMIT() asm volatile("cp.async.commit_group;" ::: "memory")
#define CP_WAIT(n)  asm volatile("cp.async.wait_group %0;" :: "n"(n) : "memory")

__device__ __forceinline__ void ldsm4(uint32_t* r, uint32_t addr) {
    asm volatile("ldmatrix.sync.aligned.m8n8.x4.shared.b16 {%0,%1,%2,%3}, [%4];"
                 : "=r"(r[0]), "=r"(r[1]), "=r"(r[2]), "=r"(r[3]) : "r"(addr));
}
__device__ __forceinline__ void mma_f16(float* d, const uint32_t* a, const uint32_t* b) {
    asm volatile(
        "mma.sync.aligned.m16n8k16.row.col.f32.f16.f16.f32 "
        "{%0,%1,%2,%3}, {%4,%5,%6,%7}, {%8,%9}, {%0,%1,%2,%3};"
        : "+f"(d[0]), "+f"(d[1]), "+f"(d[2]), "+f"(d[3])
        : "r"(a[0]), "r"(a[1]), "r"(a[2]), "r"(a[3]), "r"(b[0]), "r"(b[1]));
}
#define STS128(addr, v) \
    asm volatile("st.shared.v4.b32 [%0], {%1,%2,%3,%4};" \
                 :: "r"(addr), "r"((v).x), "r"((v).y), "r"((v).z), "r"((v).w) : "memory")

__device__ __forceinline__ uint32_t swz(uint32_t off) { return off ^ ((off >> 3) & 0x70); }

// ============================ fp16 2-way split =============================
__device__ __forceinline__ void split2h(float v, __half& h, __half& l) {
    h = __float2half(v);
    l = __float2half(v - __half2float(h));
}

// ---------------------------------------------------------------------------
// Combined weight prep: wcat^T -> g_wc [128][512] (+bcat); W_out^T hi -> g_woh.
// ---------------------------------------------------------------------------
__global__ void prep_weights_kernel(const float* __restrict__ W_off,
                                    const float* __restrict__ b_off,
                                    const float* __restrict__ W_attn,
                                    const float* __restrict__ b_attn,
                                    const float* __restrict__ W_out) {
    int id = blockIdx.x * blockDim.x + threadIdx.x;
    if (id < 128 * 256) {
        int j = id >> 8, k = id & 255;
        float v = 0.f;
        if (j < 64)       v = W_off[k * 64 + j];
        else if (j < 96)  v = W_attn[k * 32 + (j - 64)];
        __half h, l;
        split2h(v, h, l);
        g_wc[j * KS + k] = h; g_wc[j * KS + 256 + k] = l;
        if (id < P96) g_bcat[id] = (id < 64) ? b_off[id] : b_attn[id - 64];
    } else {
        int id2 = id - 128 * 256;       // over 256*256
        int n = id2 >> 8, k = id2 & 255;
        g_woh[n * C_ + k] = __float2half(W_out[k * C_ + n]);
    }
}

// ---------------------------------------------------------------------------
// Transpose v4: (B, Hh*D, H*W) fp32 -> (B, Hh, H*W, D) fp16.
// ---------------------------------------------------------------------------
__global__ void transpose_val_kernel(const float* __restrict__ val) {
    __shared__ float4 t4[64][8];
    int bh = blockIdx.y;
    int p0 = blockIdx.x * 64;
    int tid = threadIdx.x;
    int dl = tid >> 6;         // 0..3
    int pl = tid & 63;         // 0..63
    const float* src = val + ((size_t)bh * 32) * HW_ + p0 + pl;
#pragma unroll
    for (int i = 0; i < 2; i++) {
        int dq = dl * 2 + i;   // 0..7
        float4 v;
        v.x = src[(size_t)(dq * 4 + 0) * HW_];
        v.y = src[(size_t)(dq * 4 + 1) * HW_];
        v.z = src[(size_t)(dq * 4 + 2) * HW_];
        v.w = src[(size_t)(dq * 4 + 3) * HW_];
        t4[pl][dq ^ (pl & 7)] = v;
    }
    __syncthreads();
    int c  = tid & 7;          // output d-quad
    int pw = tid >> 3;         // 0..31
    __half* dst = g_valth + (size_t)bh * HW_ * 32 + (size_t)p0 * 32;
#pragma unroll
    for (int i = 0; i < 2; i++) {
        int p = pw + i * 32;
        float4 v = t4[p][c ^ (p & 7)];
        __half2 h01 = __floats2half2_rn(v.x, v.y);
        __half2 h23 = __floats2half2_rn(v.z, v.w);
        uint2 u;
        u.x = *reinterpret_cast<uint32_t*>(&h01);
        u.y = *reinterpret_cast<uint32_t*>(&h23);
        *(uint2*)&dst[(size_t)p * 32 + c * 4] = u;
    }
}

// ===========================================================================
// GEMM-1 FUSED: params[M,96] = q_hi@w_hi + q_hi@w_lo + q_lo@w_hi + bcat.
// Reads fp32 query directly; splits in regs; 3 mma passes per 64-col chunk.
// ===========================================================================
__global__ __launch_bounds__(256)
void g1_fused_kernel(const float* __restrict__ Q,
                     const __half* __restrict__ WC,
                     const float* __restrict__ bias,
                     float* __restrict__ Cm) {
    extern __shared__ char dyn_raw[];
    const uint32_t raw = smem_u32(dyn_raw);
    const uint32_t sb  = (raw + 1023) & ~1023u;
    const uint32_t A_hi = sb;
    const uint32_t A_lo = sb + 16384;
    const uint32_t Bb   = sb + 32768;    // [st][whi|wlo] 16KB each

    const int tid  = threadIdx.x;
    const int wid  = tid >> 5;
    const int lane = tid & 31;
    const int row0 = blockIdx.y * 128;
    const int wm   = (wid >> 2) * 64;
    const int wn   = (wid & 3) * 32;

    float acc[4][4][4];
#pragma unroll
    for (int mi = 0; mi < 4; mi++)
#pragma unroll
        for (int ni = 0; ni < 4; ni++)
#pragma unroll
            for (int v = 0; v < 4; v++) acc[mi][ni][v] = 0.f;

    const int lrow = tid >> 3;          // 0..31
    const int lblk = tid & 7;           // 16B chunk

    auto loadB = [&](int c, int st) {
        uint32_t bh = Bb + st * 32768;
        uint32_t bl = bh + 16384;
        const __half* g1 = WC + (size_t)lrow * KS + c * 64 + lblk * 8;        // w_hi
        const __half* g2 = WC + (size_t)lrow * KS + 256 + c * 64 + lblk * 8;  // w_lo
#pragma unroll
        for (int i = 0; i < 4; i++) {
            int r = lrow + i * 32;
            cp16(bh + swz(r * 128 + lblk * 16), g1 + (size_t)i * 32 * KS);
            cp16(bl + swz(r * 128 + lblk * 16), g2 + (size_t)i * 32 * KS);
        }
        CP_COMMIT();
    };

    loadB(0, 0);
    loadB(1, 1);

    for (int c = 0; c < 4; c++) {
        __syncthreads();                 // previous compute done reading A tiles
#pragma unroll
        for (int v = tid; v < 1024; v += 256) {
            int r = v >> 3, blk = v & 7;
            const float* ap = Q + (size_t)(row0 + r) * 256 + c * 64 + blk * 8;
            float4 f0 = *(const float4*)(ap);
            float4 f1 = *(const float4*)(ap + 4);
            __half h[8], l[8];
            split2h(f0.x, h[0], l[0]); split2h(f0.y, h[1], l[1]);
            split2h(f0.z, h[2], l[2]); split2h(f0.w, h[3], l[3]);
            split2h(f1.x, h[4], l[4]); split2h(f1.y, h[5], l[5]);
            split2h(f1.z, h[6], l[6]); split2h(f1.w, h[7], l[7]);
            uint4 uh, ul;
            uint32_t* ph = &uh.x;
            uint32_t* pl = &ul.x;
#pragma unroll
            for (int j = 0; j < 4; j++) {
                __half2 a(h[2 * j], h[2 * j + 1]);
                __half2 b(l[2 * j], l[2 * j + 1]);
                ph[j] = *reinterpret_cast<uint32_t*>(&a);
                pl[j] = *reinterpret_cast<uint32_t*>(&b);
            }
            uint32_t so = swz(r * 128 + blk * 16);
            STS128(A_hi + so, uh);
            STS128(A_lo + so, ul);
        }
        if (c + 1 < 4) { loadB(c + 1, (c + 1) & 1); CP_WAIT(1); }
        else          { CP_WAIT(0); }
        __syncthreads();

        const uint32_t bhi = Bb + (c & 1) * 32768;
        const uint32_t blo = bhi + 16384;
        const uint32_t pa[3] = {A_hi, A_hi, A_lo};
        const uint32_t pb[3] = {bhi,  blo,  bhi};
#pragma unroll
        for (int pass = 0; pass < 3; pass++) {
            const uint32_t a_t = pa[pass];
            const uint32_t b_t = pb[pass];
#pragma unroll
            for (int ks = 0; ks < 4; ks++) {
                uint32_t af[4][4];
#pragma unroll
                for (int mi = 0; mi < 4; mi++) {
                    int r  = wm + mi * 16 + (lane & 15);
                    int kc = ks * 16 + (lane >> 4) * 8;
                    ldsm4(af[mi], a_t + swz(r * 128 + kc * 2));
                }
                uint32_t bf[4][2];
#pragma unroll
                for (int nj = 0; nj < 2; nj++) {
                    int gsel = lane >> 3;
                    int nrow = wn + (nj * 2 + (gsel >> 1)) * 8 + (lane & 7);
                    int kc   = ks * 16 + (gsel & 1) * 8;
                    uint32_t r4[4];
                    ldsm4(r4, b_t + swz(nrow * 128 + kc * 2));
                    bf[nj * 2][0]     = r4[0];
                    bf[nj * 2][1]     = r4[1];
                    bf[nj * 2 + 1][0] = r4[2];
                    bf[nj * 2 + 1][1] = r4[3];
                }
#pragma unroll
                for (int mi = 0; mi < 4; mi++)
#pragma unroll
                    for (int ni = 0; ni < 4; ni++)
                        mma_f16(acc[mi][ni], af[mi], bf[ni]);
            }
        }
    }

    const int r = lane >> 2;
    const int q = lane & 3;
#pragma unroll
    for (int mi = 0; mi < 4; mi++) {
#pragma unroll
        for (int ni = 0; ni < 4; ni++) {
            int row = row0 + wm + mi * 16 + r;
            int c   = wn + ni * 8 + 2 * q;
            if (c < P96) {
                float b0 = bias[c], b1 = bias[c + 1];
                float2 v0 = make_float2(acc[mi][ni][0] + b0, acc[mi][ni][1] + b1);
                float2 v1 = make_float2(acc[mi][ni][2] + b0, acc[mi][ni][3] + b1);
                *(float2*)&Cm[(size_t)row * P96 + c]       = v0;
                *(float2*)&Cm[(size_t)(row + 8) * P96 + c] = v1;
            }
        }
    }
}

// ===========================================================================
// GEMM-2: out[M,256] = a_h @ wo_h^T + b_out.  K=256 (4 chunks of 64),
// A = g_ah [M][256] fp16, B = g_woh [256][256]. 3-stage cp.async pipeline.
// ===========================================================================
__global__ __launch_bounds__(256, 2)
void f16_gemm2(const __half* __restrict__ A,
               const __half* __restrict__ BT,
               const float* __restrict__ bias,
               float* __restrict__ Cm) {
    extern __shared__ char dyn_raw[];
    const uint32_t raw = smem_u32(dyn_raw);
    const uint32_t sb  = (raw + 1023) & ~1023u;

    const int tid  = threadIdx.x;
    const int wid  = tid >> 5;
    const int lane = tid & 31;
    const int row0 = blockIdx.y * 128;
    const int col0 = blockIdx.x * 128;
    const int wm   = (wid >> 2) * 64;
    const int wn   = (wid & 3) * 32;

    float acc[4][4][4];
#pragma unroll
    for (int mi = 0; mi < 4; mi++)
#pragma unroll
        for (int ni = 0; ni < 4; ni++)
#pragma unroll
            for (int v = 0; v < 4; v++) acc[mi][ni][v] = 0.f;

    const int lrow = tid >> 3;
    const int lblk = tid & 7;

    auto load_stage = [&](int c, int st) {
        uint32_t a_t = sb + st * 32768;
        uint32_t b_t = a_t + 16384;
        const __half* ag = A  + (size_t)(row0 + lrow) * C_ + c * 64 + lblk * 8;
        const __half* bg = BT + (size_t)(col0 + lrow) * C_ + c * 64 + lblk * 8;
#pragma unroll
        for (int i = 0; i < 4; i++) {
            int r = lrow + i * 32;
            cp16(a_t + swz(r * 128 + lblk * 16), ag + (size_t)i * 32 * C_);
            cp16(b_t + swz(r * 128 + lblk * 16), bg + (size_t)i * 32 * C_);
        }
        CP_COMMIT();
    };

    load_stage(0, 0);
    load_stage(1, 1);

    for (int c = 0; c < 4; c++) {
        if (c + 1 < 4) { CP_WAIT(1); } else { CP_WAIT(0); }
        __syncthreads();
        if (c + 2 < 4) load_stage(c + 2, (c + 2) % 3);

        const uint32_t a_t = sb + (c % 3) * 32768;
        const uint32_t b_t = a_t + 16384;
#pragma unroll
        for (int ks = 0; ks < 4; ks++) {
            uint32_t af[4][4];
#pragma unroll
            for (int mi = 0; mi < 4; mi++) {
                int r  = wm + mi * 16 + (lane & 15);
                int kc = ks * 16 + (lane >> 4) * 8;
                ldsm4(af[mi], a_t + swz(r * 128 + kc * 2));
            }
            uint32_t bf[4][2];
#pragma unroll
            for (int nj = 0; nj < 2; nj++) {
                int gsel = lane >> 3;
                int nrow = wn + (nj * 2 + (gsel >> 1)) * 8 + (lane & 7);
                int kc   = ks * 16 + (gsel & 1) * 8;
                uint32_t r4[4];
                ldsm4(r4, b_t + swz(nrow * 128 + kc * 2));
                bf[nj * 2][0]     = r4[0];
                bf[nj * 2][1]     = r4[1];
                bf[nj * 2 + 1][0] = r4[2];
                bf[nj * 2 + 1][1] = r4[3];
            }
#pragma unroll
            for (int mi = 0; mi < 4; mi++)
#pragma unroll
                for (int ni = 0; ni < 4; ni++)
                    mma_f16(acc[mi][ni], af[mi], bf[ni]);
        }
    }

    const int r = lane >> 2;
    const int q = lane & 3;
#pragma unroll
    for (int mi = 0; mi < 4; mi++) {
#pragma unroll
        for (int ni = 0; ni < 4; ni++) {
            int row = row0 + wm + mi * 16 + r;
            int c   = col0 + wn + ni * 8 + 2 * q;
            float b0 = bias[c], b1 = bias[c + 1];
            float2 v0 = make_float2(acc[mi][ni][0] + b0, acc[mi][ni][1] + b1);
            float2 v1 = make_float2(acc[mi][ni][2] + b0, acc[mi][ni][3] + b1);
            *(float2*)&Cm[(size_t)row * C_ + c]       = v0;
            *(float2*)&Cm[(size_t)(row + 8) * C_ + c] = v1;
        }
    }
}

// ---------------------------------------------------------------------------
// Sampling v6: v3 dataflow + vectorized param loads + fp16 packed accumulate.
// HALF-WARP <-> (b, n, head); corner g=(lane>>2)&3; lane covers 8 channels.
// Logits via one float4 LDG; offsets via two float4 LDG. Phase-3 uses HFMA2
// against a broadcast half2 weight (acc stays packed fp16); reduction is
// shfl+HADD2; store is the raw uint4 (no conversions).
// ---------------------------------------------------------------------------
__global__ void sample_kernel(const float* __restrict__ refp) {
    int gw   = (blockIdx.x * blockDim.x + threadIdx.x) >> 5;
    int lane = threadIdx.x & 31;
    int sub  = lane >> 4;
    int it   = gw * 2 + sub;
    int h    = it & 7;
    int bn   = it >> 3;
    int b    = bn >> 13;

    int g  = (lane >> 2) & 3;
    int gx = g & 1, gy = g >> 1;
    int d8 = (lane & 3) * 8;

    const float* pr = g_params + (size_t)bn * P96;

    float2 rp = *(const float2*)&refp[2 * bn];
    float bx = 2.f * rp.x;
    float by = 2.f * rp.y;

    // logits: one 16B load (row base 384B-aligned, offset 256+16h)
    float4 lg = *(const float4*)(pr + 64 + h * 4);
    float mx = fmaxf(fmaxf(lg.x, lg.y), fmaxf(lg.z, lg.w));
    float e0 = __expf(lg.x - mx), e1 = __expf(lg.y - mx);
    float e2 = __expf(lg.z - mx), e3 = __expf(lg.w - mx);
    float inv = 1.f / (e0 + e1 + e2 + e3);
    float aw[4] = {e0 * inv, e1 * inv, e2 * inv, e3 * inv};

    // offsets: two 16B loads: {ox0,oy0,ox1,oy1}, {ox2,oy2,ox3,oy3}
    float4 o01 = *(const float4*)(pr + h * 8);
    float4 o23 = *(const float4*)(pr + h * 8 + 4);
    float oxv[4] = {o01.x, o01.z, o23.x, o23.z};
    float oyv[4] = {o01.y, o01.w, o23.y, o23.w};

    const __half* vb = g_valth + (size_t)(b * NH_ + h) * HW_ * 32;

    __half2 wch[4];
    int idxv[4];
#pragma unroll
    for (int p = 0; p < 4; p++) {
        float x = fmaf(bx + oxv[p], (float)W_ * 0.5f, -0.5f);
        float y = fmaf(by + oyv[p], (float)H_ * 0.5f, -0.5f);
        float x0f = floorf(x), y0f = floorf(y);
        float wx = x - x0f, wy = y - y0f;
        int xc = (int)x0f + gx;
        int yc = (int)y0f + gy;
        float wcx = gx ? wx : 1.f - wx;
        float wcy = gy ? wy : 1.f - wy;
        bool valid = (xc >= 0) & (xc < W_) & (yc >= 0) & (yc < H_);
        float wc = valid ? (wcx * wcy * aw[p]) : 0.f;
        idxv[p] = valid ? (yc * W_ + xc) : 0;
        wch[p]  = __half2half2(__float2half(wc));
    }
    // all 4 gathers in flight
    uint4 vv[4];
#pragma unroll
    for (int p = 0; p < 4; p++)
        vv[p] = *(const uint4*)&vb[(size_t)idxv[p] * 32 + d8];

    // packed fp16 accumulate: 4 HFMA2 per point
    __half2 acc2[4];
#pragma unroll
    for (int j = 0; j < 4; j++) acc2[j] = __half2half2(__float2half(0.f));
#pragma unroll
    for (int p = 0; p < 4; p++) {
        const uint32_t* u = &vv[p].x;
#pragma unroll
        for (int j = 0; j < 4; j++)
            acc2[j] = __hfma2(wch[p], *reinterpret_cast<const __half2*>(&u[j]), acc2[j]);
    }

    // reduce across corner groups (xor 4, 8) in packed fp16
#pragma unroll
    for (int off = 4; off <= 8; off <<= 1) {
#pragma unroll
        for (int j = 0; j < 4; j++) {
            uint32_t au = *reinterpret_cast<uint32_t*>(&acc2[j]);
            uint32_t bu = __shfl_xor_sync(0xffffffffu, au, off);
            acc2[j] = __hadd2(acc2[j], *reinterpret_cast<__half2*>(&bu));
        }
    }

    if (g == 0) {
        uint4 uh;
        uh.x = *reinterpret_cast<uint32_t*>(&acc2[0]);
        uh.y = *reinterpret_cast<uint32_t*>(&acc2[1]);
        uh.z = *reinterpret_cast<uint32_t*>(&acc2[2]);
        uh.w = *reinterpret_cast<uint32_t*>(&acc2[3]);
        *(uint4*)&g_ah[(size_t)bn * C_ + h * 32 + d8] = uh;
    }
}

// ---------------------------------------------------------------------------
extern "C" void kernel_launch(void* const* d_in, const int* in_sizes, int n_in,
                              void* d_out, int out_size) {
    const float* query  = (const float*)d_in[0];
    const float* refp   = (const float*)d_in[1];
    const float* value  = (const float*)d_in[2];
    const float* W_off  = (const float*)d_in[3];
    const float* b_off  = (const float*)d_in[4];
    const float* W_attn = (const float*)d_in[5];
    const float* b_attn = (const float*)d_in[6];
    const float* W_out  = (const float*)d_in[7];
    const float* b_out  = (const float*)d_in[8];
    float* out = (float*)d_out;

    __half *wc, *woh, *ah;
    float *params, *bcat;
    cudaGetSymbolAddress((void**)&wc, g_wc);
    cudaGetSymbolAddress((void**)&woh, g_woh);
    cudaGetSymbolAddress((void**)&ah, g_ah);
    cudaGetSymbolAddress((void**)&params, g_params);
    cudaGetSymbolAddress((void**)&bcat, g_bcat);

    const int SMEM_G1 = 32768 + 65536 + 1024;   // A hi/lo + B 2-stage + pad
    const int SMEM_G2 = 3 * 32768 + 1024;       // 3-stage pipeline + pad
    cudaFuncSetAttribute(g1_fused_kernel,
                         cudaFuncAttributeMaxDynamicSharedMemorySize, SMEM_G1);
    cudaFuncSetAttribute(f16_gemm2,
                         cudaFuncAttributeMaxDynamicSharedMemorySize, SMEM_G2);

    prep_weights_kernel<<<(128 * 256 + 256 * 256) / 256, 256>>>(
        W_off, b_off, W_attn, b_attn, W_out);
    transpose_val_kernel<<<dim3(HW_ / 64, B_ * NH_), 256>>>(value);

    // GEMM-1 (fused split): params[M,96]
    g1_fused_kernel<<<dim3(1, M_ / 128), 256, SMEM_G1>>>(query, wc, bcat, params);

    // 2 items per warp -> 16 items per 256-thread block
    sample_kernel<<<(B_ * NH_ * N_) / 16, 256>>>(refp);

    // GEMM-2: out[M,256] = a_h @ wo_h + b_out  (K=256)
    f16_gemm2<<<dim3(2, M_ / 128), 256, SMEM_G2>>>(ah, woh, b_out, out);
}